// round 11
// baseline (speedup 1.0000x reference)
#include <cuda_runtime.h>
#include <math_constants.h>

// Problem shape (fixed): B=8, N=M=8192, D=3, fp32, scalar output.
// Exact grid NN, 3-phase cascade: ring0/1 (all) -> rings2..6 (tail) -> brute.
#define BB 8
#define PPS 8192                 // points per (batch, side)
#define BPTS (BB * PPS)          // 65536 points per side
#define NQ (2 * BPTS)            // 131072 queries (both directions)
#define G 32                     // grid cells per axis (power of 2)
#define CELLS (G * G * G)        // 32768
#define NSEG (BB * 2)            // 16 (batch, side) segments
#define TOTC (NSEG * CELLS)      // 524288 cells total
#define H 0.25f
#define INV_H 4.0f
#define ORIG 4.0f                // grid covers [-4,4); outside clamps (exact-safe)
#define SCAN_BLOCKS 128          // 128 * 4096 == TOTC
#define R2_CAP 6                 // phase-2 max ring; beyond -> brute

// Static scratch (no allocations allowed). Zero at module load;
// counters re-zeroed each call by later kernels (deterministic replays).
__device__ int    g_cnt[TOTC];       // cell counts, then scatter cursors
__device__ int    g_start[TOTC + 1]; // global exclusive scan of counts
__device__ int    g_bsum[SCAN_BLOCKS]; // per-scan-block sums
__device__ float4 g_pts[NQ];         // cell-sorted points (x,y,z, 0.5*|p|^2)
__device__ float  g_best[NQ];        // per-query clamped min d' = d^2/2
__device__ int    g_ovf[NQ];         // phase-1 overflow query ids
__device__ int    g_ovfcnt;
__device__ int    g_ovf2[NQ];        // phase-2 overflow query ids
__device__ int    g_ovfcnt2;

__device__ __forceinline__ int cell_of(float x, float y, float z, int seg) {
    int cx = min(max((int)((x + ORIG) * INV_H), 0), G - 1);
    int cy = min(max((int)((y + ORIG) * INV_H), 0), G - 1);
    int cz = min(max((int)((z + ORIG) * INV_H), 0), G - 1);
    return (seg << 15) | (cz << 10) | (cy << 5) | cx;
}

// ---- build phase ----------------------------------------------------------
__global__ void count_kernel(const float* __restrict__ gts,
                             const float* __restrict__ preds) {
    int t = blockIdx.x * 256 + threadIdx.x;            // 0..131071
    int db = t < BPTS ? 0 : 1;
    int pi = t - db * BPTS;
    const float* src = db ? preds : gts;
    float x = src[3 * pi], y = src[3 * pi + 1], z = src[3 * pi + 2];
    int seg = (pi >> 13) * 2 + db;
    atomicAdd(&g_cnt[cell_of(x, y, z, seg)], 1);
}

// Each scan block owns 4096 cells; thread owns 16 contiguous cells.
__global__ void scan1_kernel() {
    __shared__ int red[256];
    const int tid = threadIdx.x;
    const int base = blockIdx.x * 4096 + tid * 16;
    const int4* p = reinterpret_cast<const int4*>(g_cnt + base);
    int s = 0;
#pragma unroll
    for (int j = 0; j < 4; j++) {
        int4 v = p[j];
        s += v.x + v.y + v.z + v.w;
    }
    red[tid] = s;
    __syncthreads();
    for (int o = 128; o >= 1; o >>= 1) {
        if (tid < o) red[tid] += red[tid + o];
        __syncthreads();
    }
    if (tid == 0) g_bsum[blockIdx.x] = red[0];
}

// Fused inter-block prefix (redundant per block over 128 sums) + intra scan
// + write of g_start and scatter cursors.
__global__ void scan3_kernel() {
    __shared__ int s[256];
    __shared__ int basesum;
    const int tid = threadIdx.x;
    const int bid = blockIdx.x;

    s[tid] = (tid < SCAN_BLOCKS && tid < bid) ? g_bsum[tid] : 0;
    __syncthreads();
    for (int o = 128; o >= 1; o >>= 1) {
        if (tid < o) s[tid] += s[tid + o];
        __syncthreads();
    }
    if (tid == 0) basesum = s[0];
    __syncthreads();
    const int blkbase = basesum;
    __syncthreads();                         // s[] reused below

    const int base = bid * 4096 + tid * 16;
    int c[16];
    const int4* p = reinterpret_cast<const int4*>(g_cnt + base);
#pragma unroll
    for (int j = 0; j < 4; j++) {
        int4 v = p[j];
        c[4 * j + 0] = v.x; c[4 * j + 1] = v.y;
        c[4 * j + 2] = v.z; c[4 * j + 3] = v.w;
    }
    int tsum = 0;
#pragma unroll
    for (int j = 0; j < 16; j++) tsum += c[j];
    s[tid] = tsum;
    __syncthreads();
    for (int off = 1; off < 256; off <<= 1) {
        int add = (tid >= off) ? s[tid - off] : 0;
        __syncthreads();
        s[tid] += add;
        __syncthreads();
    }
    int run = blkbase + s[tid] - tsum;       // global exclusive offset
#pragma unroll
    for (int j = 0; j < 16; j++) {
        g_start[base + j] = run;
        g_cnt[base + j] = run;               // scatter cursor
        run += c[j];
    }
    if (bid == 0 && tid == 0) g_start[TOTC] = NQ;
}

__global__ void scatter_kernel(const float* __restrict__ gts,
                               const float* __restrict__ preds) {
    int t = blockIdx.x * 256 + threadIdx.x;
    int db = t < BPTS ? 0 : 1;
    int pi = t - db * BPTS;
    const float* src = db ? preds : gts;
    float x = src[3 * pi], y = src[3 * pi + 1], z = src[3 * pi + 2];
    int seg = (pi >> 13) * 2 + db;
    int pos = atomicAdd(&g_cnt[cell_of(x, y, z, seg)], 1);
    g_pts[pos] = make_float4(x, y, z, 0.5f * (x * x + y * y + z * z));
}

// ---- query phase ----------------------------------------------------------
// Candidate scan with two fmin accumulators (short dep chains, 2x load MLP).
__device__ __forceinline__ void scan_range(int s, int e,
                                           float nx, float ny, float nz, float qw,
                                           float& b0, float& b1) {
    int k = s;
    for (; k + 1 < e; k += 2) {
        float4 p = g_pts[k];
        float4 p2 = g_pts[k + 1];
        float d = qw + p.w;
        d = fmaf(nx, p.x, d);
        d = fmaf(ny, p.y, d);
        d = fmaf(nz, p.z, d);
        float d2 = qw + p2.w;
        d2 = fmaf(nx, p2.x, d2);
        d2 = fmaf(ny, p2.y, d2);
        d2 = fmaf(nz, p2.z, d2);
        b0 = fminf(b0, d);
        b1 = fminf(b1, d2);
    }
    if (k < e) {
        float4 p = g_pts[k];
        float d = qw + p.w;
        d = fmaf(nx, p.x, d);
        d = fmaf(ny, p.y, d);
        d = fmaf(nz, p.z, d);
        b0 = fminf(b0, d);
    }
}

// Shared helper: decode query id -> geometry.
struct QInfo {
    float nx, ny, nz, qw, fmin;
    int cx, cy, cz, tbase;
};
__device__ __forceinline__ QInfo decode_query(int t) {
    const int dir = t >> 16;
    const int qi = t & 65535;
    const int b = qi >> 13, i = qi & 8191;
    const int qseg = b * 2 + dir;
    const int tseg = b * 2 + (1 - dir);
    float4 q = g_pts[qseg * PPS + i];
    QInfo s;
    s.nx = -q.x; s.ny = -q.y; s.nz = -q.z; s.qw = q.w;
    s.cx = min(max((int)((q.x + ORIG) * INV_H), 0), G - 1);
    s.cy = min(max((int)((q.y + ORIG) * INV_H), 0), G - 1);
    s.cz = min(max((int)((q.z + ORIG) * INV_H), 0), G - 1);
    const float fx = (q.x + ORIG) - s.cx * H;
    const float fy = (q.y + ORIG) - s.cy * H;
    const float fz = (q.z + ORIG) - s.cz * H;
    s.fmin = fminf(fminf(fminf(fx, H - fx), fminf(fy, H - fy)),
                   fminf(fz, H - fz));
    s.tbase = tseg << 15;
    return s;
}

// Phase 1: uniform ring-0/1 for every query. d' = d^2/2.
// Bound after ring 1: unexplored points are >= H + fmin away. ~96-98% converge.
// Also re-zeros g_cnt for the next call (exactly 1 int4 per thread).
__global__ void __launch_bounds__(256) query_kernel() {
    const int t = blockIdx.x * 256 + threadIdx.x;      // 0..131071
    reinterpret_cast<int4*>(g_cnt)[t] = make_int4(0, 0, 0, 0);

    const QInfo s = decode_query(t);
    float b0 = CUDART_INF_F, b1 = CUDART_INF_F;

    const int x0 = max(s.cx - 1, 0), x1 = min(s.cx + 1, G - 1);
    const int zlo = max(s.cz - 1, 0), zhi = min(s.cz + 1, G - 1);
    const int ylo = max(s.cy - 1, 0), yhi = min(s.cy + 1, G - 1);
    for (int z = zlo; z <= zhi; z++) {
        for (int y = ylo; y <= yhi; y++) {
            const int rowb = s.tbase | (z << 10) | (y << 5);
            scan_range(g_start[rowb + x0], g_start[rowb + x1 + 1],
                       s.nx, s.ny, s.nz, s.qw, b0, b1);
        }
    }

    const float best = fmaxf(fminf(b0, b1), 0.0f);
    g_best[t] = best;                                   // partial if overflowing
    const float bnd = H + s.fmin;
    if (!(2.0f * best <= bnd * bnd)) {
        int pos = atomicAdd(&g_ovfcnt, 1);
        g_ovf[pos] = t;
    }
}

// Phase 2: rings 2..R2_CAP for the compacted overflow set. Warps here are
// 100% slow queries -> no wasted lanes. Resumes from phase-1 best.
__global__ void __launch_bounds__(256) query2_kernel() {
    const int cnt = g_ovfcnt;
    for (int j = blockIdx.x * 256 + threadIdx.x; j < cnt; j += 32 * 256) {
        const int t = g_ovf[j];
        const QInfo s = decode_query(t);
        float b0 = g_best[t], b1 = CUDART_INF_F;
        bool done = false;

        for (int r = 2; r <= R2_CAP && !done; r++) {
            const int z0 = max(s.cz - r, 0), z1 = min(s.cz + r, G - 1);
            const int y0 = max(s.cy - r, 0), y1 = min(s.cy + r, G - 1);
            const int x0 = max(s.cx - r, 0), x1 = min(s.cx + r, G - 1);
            for (int z = z0; z <= z1; z++) {
                const bool zf = (z == s.cz - r) || (z == s.cz + r);
                for (int y = y0; y <= y1; y++) {
                    const bool yf = (y == s.cy - r) || (y == s.cy + r);
                    const int rowb = s.tbase | (z << 10) | (y << 5);
                    if (zf || yf) {
                        scan_range(g_start[rowb + x0], g_start[rowb + x1 + 1],
                                   s.nx, s.ny, s.nz, s.qw, b0, b1);
                    } else {
#pragma unroll
                        for (int u = 0; u < 2; u++) {
                            const int x = u ? s.cx + r : s.cx - r;
                            if ((unsigned)x >= (unsigned)G) continue;
                            scan_range(g_start[rowb + x], g_start[rowb + x + 1],
                                       s.nx, s.ny, s.nz, s.qw, b0, b1);
                        }
                    }
                }
            }
            const float bnd = r * H + s.fmin;
            if (2.0f * fminf(b0, b1) <= bnd * bnd) done = true;
        }

        g_best[t] = fmaxf(fminf(b0, b1), 0.0f);
        if (!done) {
            int pos = atomicAdd(&g_ovfcnt2, 1);   // extreme tail (~tens)
            g_ovf2[pos] = t;
        }
    }
}

// Phase 3: warp-per-query brute force for the extreme tail (tiny count).
__global__ void __launch_bounds__(256) brute_kernel() {
    const int cnt = g_ovfcnt2;
    const int lane = threadIdx.x & 31;
    const int warp = (blockIdx.x * 256 + threadIdx.x) >> 5;
    for (int j = warp; j < cnt; j += 512) {
        const int t = g_ovf2[j];
        const int dir = t >> 16;
        const int qi = t & 65535;
        const int b = qi >> 13, i = qi & 8191;
        const int qseg = b * 2 + dir;
        const int tseg = b * 2 + (1 - dir);

        float4 q = g_pts[qseg * PPS + i];
        const float nx = -q.x, ny = -q.y, nz = -q.z, qw = q.w;
        const float4* tp = g_pts + tseg * PPS;

        float best = CUDART_INF_F;
        for (int k = lane; k < PPS; k += 32) {
            float4 p = tp[k];
            float d = qw + p.w;
            d = fmaf(nx, p.x, d);
            d = fmaf(ny, p.y, d);
            d = fmaf(nz, p.z, d);
            best = fminf(best, d);
        }
#pragma unroll
        for (int o = 16; o >= 1; o >>= 1)
            best = fminf(best, __shfl_xor_sync(0xFFFFFFFFu, best, o));
        if (lane == 0) g_best[t] = fmaxf(best, 0.0f);
    }
}

// Single-block deterministic sum; resets overflow counters for next call.
__global__ void final_kernel(float* __restrict__ out) {
    __shared__ float sred[1024];
    const int tid = threadIdx.x;
    float acc = 0.0f;
    const float4* p = reinterpret_cast<const float4*>(g_best);
#pragma unroll 8
    for (int i = tid; i < NQ / 4; i += 1024) {
        float4 v = p[i];
        acc += (v.x + v.y) + (v.z + v.w);
    }
    sred[tid] = acc;
    __syncthreads();
    for (int o = 512; o >= 1; o >>= 1) {
        if (tid < o) sred[tid] += sred[tid + o];
        __syncthreads();
    }
    if (tid == 0) {
        // d^2 = 2*d'; each direction is a mean over 65536 points.
        out[0] = sred[0] * (2.0f / 65536.0f);
        g_ovfcnt = 0;
        g_ovfcnt2 = 0;
    }
}

extern "C" void kernel_launch(void* const* d_in, const int* in_sizes, int n_in,
                              void* d_out, int out_size) {
    const float* gts   = (const float*)d_in[0];
    const float* preds = (const float*)d_in[1];
    float* out = (float*)d_out;

    count_kernel<<<512, 256>>>(gts, preds);
    scan1_kernel<<<SCAN_BLOCKS, 256>>>();
    scan3_kernel<<<SCAN_BLOCKS, 256>>>();
    scatter_kernel<<<512, 256>>>(gts, preds);
    query_kernel<<<512, 256>>>();
    query2_kernel<<<32, 256>>>();
    brute_kernel<<<64, 256>>>();
    final_kernel<<<1, 1024>>>(out);
}

// round 12
// speedup vs baseline: 2.0532x; 2.0532x over previous
#include <cuda_runtime.h>
#include <math_constants.h>

// Problem shape (fixed): B=8, N=M=8192, D=3, fp32, scalar output.
// Exact grid NN, 3-phase cascade:
//   P1: ring0/1, thread-per-query (uniform work)
//   P2: r<=4 cube, WARP-per-query (lanes split rows -> parallel lookups)
//   P3: brute force, warp-per-query (extreme tail, ~hundreds)
#define BB 8
#define PPS 8192                 // points per (batch, side)
#define BPTS (BB * PPS)          // 65536 points per side
#define NQ (2 * BPTS)            // 131072 queries (both directions)
#define G 32                     // grid cells per axis (power of 2)
#define CELLS (G * G * G)        // 32768
#define NSEG (BB * 2)            // 16 (batch, side) segments
#define TOTC (NSEG * CELLS)      // 524288 cells total
#define H 0.25f
#define INV_H 4.0f
#define ORIG 4.0f                // grid covers [-4,4); outside clamps (exact-safe)
#define SCAN_BLOCKS 128          // 128 * 4096 == TOTC
#define R2 4                     // phase-2 cube radius (9x9x9 cells)

// Static scratch (no allocations allowed). Zero at module load;
// counters re-zeroed each call by later kernels (deterministic replays).
__device__ int    g_cnt[TOTC];       // cell counts, then scatter cursors
__device__ int    g_start[TOTC + 1]; // global exclusive scan of counts
__device__ int    g_bsum[SCAN_BLOCKS]; // per-scan-block sums
__device__ float4 g_pts[NQ];         // cell-sorted points (x,y,z, 0.5*|p|^2)
__device__ float  g_best[NQ];        // per-query clamped min d' = d^2/2
__device__ int    g_ovf[NQ];         // phase-1 overflow query ids
__device__ int    g_ovfcnt;
__device__ int    g_ovf2[NQ];        // phase-2 overflow query ids
__device__ int    g_ovfcnt2;

__device__ __forceinline__ int cell_of(float x, float y, float z, int seg) {
    int cx = min(max((int)((x + ORIG) * INV_H), 0), G - 1);
    int cy = min(max((int)((y + ORIG) * INV_H), 0), G - 1);
    int cz = min(max((int)((z + ORIG) * INV_H), 0), G - 1);
    return (seg << 15) | (cz << 10) | (cy << 5) | cx;
}

// ---- build phase ----------------------------------------------------------
__global__ void count_kernel(const float* __restrict__ gts,
                             const float* __restrict__ preds) {
    int t = blockIdx.x * 256 + threadIdx.x;            // 0..131071
    int db = t < BPTS ? 0 : 1;
    int pi = t - db * BPTS;
    const float* src = db ? preds : gts;
    float x = src[3 * pi], y = src[3 * pi + 1], z = src[3 * pi + 2];
    int seg = (pi >> 13) * 2 + db;
    atomicAdd(&g_cnt[cell_of(x, y, z, seg)], 1);
}

// Each scan block owns 4096 cells; thread owns 16 contiguous cells.
__global__ void scan1_kernel() {
    __shared__ int red[256];
    const int tid = threadIdx.x;
    const int base = blockIdx.x * 4096 + tid * 16;
    const int4* p = reinterpret_cast<const int4*>(g_cnt + base);
    int s = 0;
#pragma unroll
    for (int j = 0; j < 4; j++) {
        int4 v = p[j];
        s += v.x + v.y + v.z + v.w;
    }
    red[tid] = s;
    __syncthreads();
    for (int o = 128; o >= 1; o >>= 1) {
        if (tid < o) red[tid] += red[tid + o];
        __syncthreads();
    }
    if (tid == 0) g_bsum[blockIdx.x] = red[0];
}

// Fused inter-block prefix (redundant per block over 128 sums) + intra scan
// + write of g_start and scatter cursors.
__global__ void scan3_kernel() {
    __shared__ int s[256];
    __shared__ int basesum;
    const int tid = threadIdx.x;
    const int bid = blockIdx.x;

    s[tid] = (tid < SCAN_BLOCKS && tid < bid) ? g_bsum[tid] : 0;
    __syncthreads();
    for (int o = 128; o >= 1; o >>= 1) {
        if (tid < o) s[tid] += s[tid + o];
        __syncthreads();
    }
    if (tid == 0) basesum = s[0];
    __syncthreads();
    const int blkbase = basesum;
    __syncthreads();                         // s[] reused below

    const int base = bid * 4096 + tid * 16;
    int c[16];
    const int4* p = reinterpret_cast<const int4*>(g_cnt + base);
#pragma unroll
    for (int j = 0; j < 4; j++) {
        int4 v = p[j];
        c[4 * j + 0] = v.x; c[4 * j + 1] = v.y;
        c[4 * j + 2] = v.z; c[4 * j + 3] = v.w;
    }
    int tsum = 0;
#pragma unroll
    for (int j = 0; j < 16; j++) tsum += c[j];
    s[tid] = tsum;
    __syncthreads();
    for (int off = 1; off < 256; off <<= 1) {
        int add = (tid >= off) ? s[tid - off] : 0;
        __syncthreads();
        s[tid] += add;
        __syncthreads();
    }
    int run = blkbase + s[tid] - tsum;       // global exclusive offset
#pragma unroll
    for (int j = 0; j < 16; j++) {
        g_start[base + j] = run;
        g_cnt[base + j] = run;               // scatter cursor
        run += c[j];
    }
    if (bid == 0 && tid == 0) g_start[TOTC] = NQ;
}

__global__ void scatter_kernel(const float* __restrict__ gts,
                               const float* __restrict__ preds) {
    int t = blockIdx.x * 256 + threadIdx.x;
    int db = t < BPTS ? 0 : 1;
    int pi = t - db * BPTS;
    const float* src = db ? preds : gts;
    float x = src[3 * pi], y = src[3 * pi + 1], z = src[3 * pi + 2];
    int seg = (pi >> 13) * 2 + db;
    int pos = atomicAdd(&g_cnt[cell_of(x, y, z, seg)], 1);
    g_pts[pos] = make_float4(x, y, z, 0.5f * (x * x + y * y + z * z));
}

// ---- query phase ----------------------------------------------------------
// Candidate scan with two fmin accumulators (short dep chains, 2x load MLP).
__device__ __forceinline__ void scan_range(int s, int e,
                                           float nx, float ny, float nz, float qw,
                                           float& b0, float& b1) {
    int k = s;
    for (; k + 1 < e; k += 2) {
        float4 p = g_pts[k];
        float4 p2 = g_pts[k + 1];
        float d = qw + p.w;
        d = fmaf(nx, p.x, d);
        d = fmaf(ny, p.y, d);
        d = fmaf(nz, p.z, d);
        float d2 = qw + p2.w;
        d2 = fmaf(nx, p2.x, d2);
        d2 = fmaf(ny, p2.y, d2);
        d2 = fmaf(nz, p2.z, d2);
        b0 = fminf(b0, d);
        b1 = fminf(b1, d2);
    }
    if (k < e) {
        float4 p = g_pts[k];
        float d = qw + p.w;
        d = fmaf(nx, p.x, d);
        d = fmaf(ny, p.y, d);
        d = fmaf(nz, p.z, d);
        b0 = fminf(b0, d);
    }
}

// Shared helper: decode query id -> geometry.
struct QInfo {
    float nx, ny, nz, qw, fmin;
    int cx, cy, cz, tbase;
};
__device__ __forceinline__ QInfo decode_query(int t) {
    const int dir = t >> 16;
    const int qi = t & 65535;
    const int b = qi >> 13, i = qi & 8191;
    const int qseg = b * 2 + dir;
    const int tseg = b * 2 + (1 - dir);
    float4 q = g_pts[qseg * PPS + i];
    QInfo s;
    s.nx = -q.x; s.ny = -q.y; s.nz = -q.z; s.qw = q.w;
    s.cx = min(max((int)((q.x + ORIG) * INV_H), 0), G - 1);
    s.cy = min(max((int)((q.y + ORIG) * INV_H), 0), G - 1);
    s.cz = min(max((int)((q.z + ORIG) * INV_H), 0), G - 1);
    const float fx = (q.x + ORIG) - s.cx * H;
    const float fy = (q.y + ORIG) - s.cy * H;
    const float fz = (q.z + ORIG) - s.cz * H;
    s.fmin = fminf(fminf(fminf(fx, H - fx), fminf(fy, H - fy)),
                   fminf(fz, H - fz));
    s.tbase = tseg << 15;
    return s;
}

// Phase 1: uniform ring-0/1 for every query (thread-per-query).
// d' = 0.5|q|^2+0.5|p|^2-q.p = d^2/2. Bound after ring 1: H + fmin.
// Also re-zeros g_cnt for the next call (exactly 1 int4 per thread).
__global__ void __launch_bounds__(256) query_kernel() {
    const int t = blockIdx.x * 256 + threadIdx.x;      // 0..131071
    reinterpret_cast<int4*>(g_cnt)[t] = make_int4(0, 0, 0, 0);

    const QInfo s = decode_query(t);
    float b0 = CUDART_INF_F, b1 = CUDART_INF_F;

    const int x0 = max(s.cx - 1, 0), x1 = min(s.cx + 1, G - 1);
    const int zlo = max(s.cz - 1, 0), zhi = min(s.cz + 1, G - 1);
    const int ylo = max(s.cy - 1, 0), yhi = min(s.cy + 1, G - 1);
    for (int z = zlo; z <= zhi; z++) {
        for (int y = ylo; y <= yhi; y++) {
            const int rowb = s.tbase | (z << 10) | (y << 5);
            scan_range(g_start[rowb + x0], g_start[rowb + x1 + 1],
                       s.nx, s.ny, s.nz, s.qw, b0, b1);
        }
    }

    const float best = fmaxf(fminf(b0, b1), 0.0f);
    g_best[t] = best;
    const float bnd = H + s.fmin;
    if (!(2.0f * best <= bnd * bnd)) {
        int pos = atomicAdd(&g_ovfcnt, 1);   // ~2-4% of queries
        g_ovf[pos] = t;
    }
}

// Phase 2: WARP-per-query over the full r<=R2 cube (9x9x9 cells = <=81
// contiguous x-rows). Lanes take rows round-robin -> all range lookups and
// candidate scans run in parallel across lanes; shfl-min at the end.
// Bound after the cube: unexplored points are >= R2*H + fmin away.
__global__ void __launch_bounds__(256) query2_kernel() {
    const int cnt = g_ovfcnt;
    const int lane = threadIdx.x & 31;
    const int gw = (blockIdx.x * 256 + threadIdx.x) >> 5;
    const int nw = gridDim.x * 8;
    for (int j = gw; j < cnt; j += nw) {
        const int t = g_ovf[j];
        const QInfo s = decode_query(t);
        float b0 = CUDART_INF_F, b1 = CUDART_INF_F;

        const int x0 = max(s.cx - R2, 0), x1 = min(s.cx + R2, G - 1);
        const int zlo = max(s.cz - R2, 0), zhi = min(s.cz + R2, G - 1);
        const int ylo = max(s.cy - R2, 0), yhi = min(s.cy + R2, G - 1);
        const int nyr = yhi - ylo + 1;
        const int nrows = (zhi - zlo + 1) * nyr;
        for (int u = lane; u < nrows; u += 32) {
            const int z = zlo + u / nyr;
            const int y = ylo + u % nyr;
            const int rowb = s.tbase | (z << 10) | (y << 5);
            scan_range(g_start[rowb + x0], g_start[rowb + x1 + 1],
                       s.nx, s.ny, s.nz, s.qw, b0, b1);
        }
        float best = fminf(b0, b1);
#pragma unroll
        for (int o = 16; o >= 1; o >>= 1)
            best = fminf(best, __shfl_xor_sync(0xFFFFFFFFu, best, o));

        if (lane == 0) {
            g_best[t] = fmaxf(best, 0.0f);
            const float bnd = R2 * H + s.fmin;
            if (!(2.0f * best <= bnd * bnd)) {
                int pos = atomicAdd(&g_ovfcnt2, 1);   // extreme tail (~hundreds)
                g_ovf2[pos] = t;
            }
        }
    }
}

// Phase 3: warp-per-query brute force over the full opposing segment.
__global__ void __launch_bounds__(256) brute_kernel() {
    const int cnt = g_ovfcnt2;
    const int lane = threadIdx.x & 31;
    const int warp = (blockIdx.x * 256 + threadIdx.x) >> 5;
    for (int j = warp; j < cnt; j += 512) {
        const int t = g_ovf2[j];
        const int dir = t >> 16;
        const int qi = t & 65535;
        const int b = qi >> 13, i = qi & 8191;
        const int qseg = b * 2 + dir;
        const int tseg = b * 2 + (1 - dir);

        float4 q = g_pts[qseg * PPS + i];
        const float nx = -q.x, ny = -q.y, nz = -q.z, qw = q.w;
        const float4* tp = g_pts + tseg * PPS;

        float best = CUDART_INF_F;
        for (int k = lane; k < PPS; k += 32) {
            float4 p = tp[k];
            float d = qw + p.w;
            d = fmaf(nx, p.x, d);
            d = fmaf(ny, p.y, d);
            d = fmaf(nz, p.z, d);
            best = fminf(best, d);
        }
#pragma unroll
        for (int o = 16; o >= 1; o >>= 1)
            best = fminf(best, __shfl_xor_sync(0xFFFFFFFFu, best, o));
        if (lane == 0) g_best[t] = fmaxf(best, 0.0f);
    }
}

// Single-block deterministic sum; resets overflow counters for next call.
__global__ void final_kernel(float* __restrict__ out) {
    __shared__ float sred[1024];
    const int tid = threadIdx.x;
    float acc = 0.0f;
    const float4* p = reinterpret_cast<const float4*>(g_best);
#pragma unroll 8
    for (int i = tid; i < NQ / 4; i += 1024) {
        float4 v = p[i];
        acc += (v.x + v.y) + (v.z + v.w);
    }
    sred[tid] = acc;
    __syncthreads();
    for (int o = 512; o >= 1; o >>= 1) {
        if (tid < o) sred[tid] += sred[tid + o];
        __syncthreads();
    }
    if (tid == 0) {
        // d^2 = 2*d'; each direction is a mean over 65536 points.
        out[0] = sred[0] * (2.0f / 65536.0f);
        g_ovfcnt = 0;
        g_ovfcnt2 = 0;
    }
}

extern "C" void kernel_launch(void* const* d_in, const int* in_sizes, int n_in,
                              void* d_out, int out_size) {
    const float* gts   = (const float*)d_in[0];
    const float* preds = (const float*)d_in[1];
    float* out = (float*)d_out;

    count_kernel<<<512, 256>>>(gts, preds);
    scan1_kernel<<<SCAN_BLOCKS, 256>>>();
    scan3_kernel<<<SCAN_BLOCKS, 256>>>();
    scatter_kernel<<<512, 256>>>(gts, preds);
    query_kernel<<<512, 256>>>();
    query2_kernel<<<128, 256>>>();
    brute_kernel<<<64, 256>>>();
    final_kernel<<<1, 1024>>>(out);
}

// round 13
// speedup vs baseline: 2.2056x; 1.0743x over previous
#include <cuda_runtime.h>
#include <math_constants.h>

// Problem shape (fixed): B=8, N=M=8192, D=3, fp32, scalar output.
// Exact grid NN, adaptive cascade with early exits at every ring:
//   P1: rings 0..1 with per-ring exits, thread-per-query
//   P2: rings 2..5 with per-ring exits, WARP-per-query (parallel lookups)
//   P3: brute force, warp-per-query (extreme tail, ~tens)
#define BB 8
#define PPS 8192                 // points per (batch, side)
#define BPTS (BB * PPS)          // 65536 points per side
#define NQ (2 * BPTS)            // 131072 queries (both directions)
#define G 32                     // grid cells per axis (power of 2)
#define CELLS (G * G * G)        // 32768
#define NSEG (BB * 2)            // 16 (batch, side) segments
#define TOTC (NSEG * CELLS)      // 524288 cells total
#define H 0.25f
#define INV_H 4.0f
#define ORIG 4.0f                // grid covers [-4,4); outside clamps (exact-safe)
#define SCAN_BLOCKS 128          // 128 * 4096 == TOTC
#define R2_CAP 5                 // phase-2 max ring; beyond -> brute

// Static scratch (no allocations allowed). Zero at module load;
// counters re-zeroed each call by later kernels (deterministic replays).
__device__ int    g_cnt[TOTC];       // cell counts, then scatter cursors
__device__ int    g_start[TOTC + 1]; // global exclusive scan of counts
__device__ int    g_bsum[SCAN_BLOCKS]; // per-scan-block sums
__device__ float4 g_pts[NQ];         // cell-sorted points (x,y,z, 0.5*|p|^2)
__device__ float  g_best[NQ];        // per-query clamped min d' = d^2/2
__device__ int    g_ovf[NQ];         // phase-1 overflow query ids
__device__ int    g_ovfcnt;
__device__ int    g_ovf2[NQ];        // phase-2 overflow query ids
__device__ int    g_ovfcnt2;

__device__ __forceinline__ int cell_of(float x, float y, float z, int seg) {
    int cx = min(max((int)((x + ORIG) * INV_H), 0), G - 1);
    int cy = min(max((int)((y + ORIG) * INV_H), 0), G - 1);
    int cz = min(max((int)((z + ORIG) * INV_H), 0), G - 1);
    return (seg << 15) | (cz << 10) | (cy << 5) | cx;
}

// ---- build phase (identical to the 94.9us R7 winner) ----------------------
__global__ void count_kernel(const float* __restrict__ gts,
                             const float* __restrict__ preds) {
    int t = blockIdx.x * 256 + threadIdx.x;            // 0..131071
    int db = t < BPTS ? 0 : 1;
    int pi = t - db * BPTS;
    const float* src = db ? preds : gts;
    float x = src[3 * pi], y = src[3 * pi + 1], z = src[3 * pi + 2];
    int seg = (pi >> 13) * 2 + db;
    atomicAdd(&g_cnt[cell_of(x, y, z, seg)], 1);
}

// Each scan block owns 4096 cells; thread owns 16 contiguous cells.
__global__ void scan1_kernel() {
    __shared__ int red[256];
    const int tid = threadIdx.x;
    const int base = blockIdx.x * 4096 + tid * 16;
    const int4* p = reinterpret_cast<const int4*>(g_cnt + base);
    int s = 0;
#pragma unroll
    for (int j = 0; j < 4; j++) {
        int4 v = p[j];
        s += v.x + v.y + v.z + v.w;
    }
    red[tid] = s;
    __syncthreads();
    for (int o = 128; o >= 1; o >>= 1) {
        if (tid < o) red[tid] += red[tid + o];
        __syncthreads();
    }
    if (tid == 0) g_bsum[blockIdx.x] = red[0];
}

// Fused inter-block prefix (redundant per block over 128 sums) + intra scan
// + write of g_start and scatter cursors.
__global__ void scan3_kernel() {
    __shared__ int s[256];
    __shared__ int basesum;
    const int tid = threadIdx.x;
    const int bid = blockIdx.x;

    s[tid] = (tid < SCAN_BLOCKS && tid < bid) ? g_bsum[tid] : 0;
    __syncthreads();
    for (int o = 128; o >= 1; o >>= 1) {
        if (tid < o) s[tid] += s[tid + o];
        __syncthreads();
    }
    if (tid == 0) basesum = s[0];
    __syncthreads();
    const int blkbase = basesum;
    __syncthreads();                         // s[] reused below

    const int base = bid * 4096 + tid * 16;
    int c[16];
    const int4* p = reinterpret_cast<const int4*>(g_cnt + base);
#pragma unroll
    for (int j = 0; j < 4; j++) {
        int4 v = p[j];
        c[4 * j + 0] = v.x; c[4 * j + 1] = v.y;
        c[4 * j + 2] = v.z; c[4 * j + 3] = v.w;
    }
    int tsum = 0;
#pragma unroll
    for (int j = 0; j < 16; j++) tsum += c[j];
    s[tid] = tsum;
    __syncthreads();
    for (int off = 1; off < 256; off <<= 1) {
        int add = (tid >= off) ? s[tid - off] : 0;
        __syncthreads();
        s[tid] += add;
        __syncthreads();
    }
    int run = blkbase + s[tid] - tsum;       // global exclusive offset
#pragma unroll
    for (int j = 0; j < 16; j++) {
        g_start[base + j] = run;
        g_cnt[base + j] = run;               // scatter cursor
        run += c[j];
    }
    if (bid == 0 && tid == 0) g_start[TOTC] = NQ;
}

__global__ void scatter_kernel(const float* __restrict__ gts,
                               const float* __restrict__ preds) {
    int t = blockIdx.x * 256 + threadIdx.x;
    int db = t < BPTS ? 0 : 1;
    int pi = t - db * BPTS;
    const float* src = db ? preds : gts;
    float x = src[3 * pi], y = src[3 * pi + 1], z = src[3 * pi + 2];
    int seg = (pi >> 13) * 2 + db;
    int pos = atomicAdd(&g_cnt[cell_of(x, y, z, seg)], 1);
    g_pts[pos] = make_float4(x, y, z, 0.5f * (x * x + y * y + z * z));
}

// ---- query phase ----------------------------------------------------------
// Candidate scan with two fmin accumulators (short dep chains, 2x load MLP).
__device__ __forceinline__ void scan_range(int s, int e,
                                           float nx, float ny, float nz, float qw,
                                           float& b0, float& b1) {
    int k = s;
    for (; k + 1 < e; k += 2) {
        float4 p = g_pts[k];
        float4 p2 = g_pts[k + 1];
        float d = qw + p.w;
        d = fmaf(nx, p.x, d);
        d = fmaf(ny, p.y, d);
        d = fmaf(nz, p.z, d);
        float d2 = qw + p2.w;
        d2 = fmaf(nx, p2.x, d2);
        d2 = fmaf(ny, p2.y, d2);
        d2 = fmaf(nz, p2.z, d2);
        b0 = fminf(b0, d);
        b1 = fminf(b1, d2);
    }
    if (k < e) {
        float4 p = g_pts[k];
        float d = qw + p.w;
        d = fmaf(nx, p.x, d);
        d = fmaf(ny, p.y, d);
        d = fmaf(nz, p.z, d);
        b0 = fminf(b0, d);
    }
}

// Shared helper: decode query id -> geometry.
struct QInfo {
    float nx, ny, nz, qw, fmin;
    int cx, cy, cz, tbase;
};
__device__ __forceinline__ QInfo decode_query(int t) {
    const int dir = t >> 16;
    const int qi = t & 65535;
    const int b = qi >> 13, i = qi & 8191;
    const int qseg = b * 2 + dir;
    const int tseg = b * 2 + (1 - dir);
    float4 q = g_pts[qseg * PPS + i];
    QInfo s;
    s.nx = -q.x; s.ny = -q.y; s.nz = -q.z; s.qw = q.w;
    s.cx = min(max((int)((q.x + ORIG) * INV_H), 0), G - 1);
    s.cy = min(max((int)((q.y + ORIG) * INV_H), 0), G - 1);
    s.cz = min(max((int)((q.z + ORIG) * INV_H), 0), G - 1);
    const float fx = (q.x + ORIG) - s.cx * H;
    const float fy = (q.y + ORIG) - s.cy * H;
    const float fz = (q.z + ORIG) - s.cz * H;
    s.fmin = fminf(fminf(fminf(fx, H - fx), fminf(fy, H - fy)),
                   fminf(fz, H - fz));
    s.tbase = tseg << 15;
    return s;
}

// Phase 1: rings 0..1 with PER-RING early exit (thread-per-query).
// d' = 0.5|q|^2+0.5|p|^2-q.p = d^2/2. After ring r, unexplored points are
// >= r*H + fmin away. Ring 0 (1 cell, bound fmin) converges the dense core
// cheaply; ring 1 (8 full rows + 2 cells) converges ~96% cumulative.
// Also re-zeros g_cnt for the next call (exactly 1 int4 per thread).
__global__ void __launch_bounds__(256) query_kernel() {
    const int t = blockIdx.x * 256 + threadIdx.x;      // 0..131071
    reinterpret_cast<int4*>(g_cnt)[t] = make_int4(0, 0, 0, 0);

    const QInfo s = decode_query(t);
    float b0 = CUDART_INF_F, b1 = CUDART_INF_F;
    bool done = false;

    // ring 0: the query's own cell
    {
        const int rowb = s.tbase | (s.cz << 10) | (s.cy << 5);
        scan_range(g_start[rowb + s.cx], g_start[rowb + s.cx + 1],
                   s.nx, s.ny, s.nz, s.qw, b0, b1);
        const float bnd = s.fmin;
        if (2.0f * fminf(b0, b1) <= bnd * bnd) done = true;
    }

    // ring 1 shell: 8 full 3-cell rows + 2 endpoint cells on the center row
    if (!done) {
        const int x0 = max(s.cx - 1, 0), x1 = min(s.cx + 1, G - 1);
        const int zlo = max(s.cz - 1, 0), zhi = min(s.cz + 1, G - 1);
        const int ylo = max(s.cy - 1, 0), yhi = min(s.cy + 1, G - 1);
        for (int z = zlo; z <= zhi; z++) {
            for (int y = ylo; y <= yhi; y++) {
                const int rowb = s.tbase | (z << 10) | (y << 5);
                if (z == s.cz && y == s.cy) {
                    // center row: endpoints only (ring 0 covered the middle)
                    if (s.cx - 1 >= 0)
                        scan_range(g_start[rowb + s.cx - 1], g_start[rowb + s.cx],
                                   s.nx, s.ny, s.nz, s.qw, b0, b1);
                    if (s.cx + 1 < G)
                        scan_range(g_start[rowb + s.cx + 1], g_start[rowb + s.cx + 2],
                                   s.nx, s.ny, s.nz, s.qw, b0, b1);
                } else {
                    scan_range(g_start[rowb + x0], g_start[rowb + x1 + 1],
                               s.nx, s.ny, s.nz, s.qw, b0, b1);
                }
            }
        }
        const float bnd = H + s.fmin;
        if (2.0f * fminf(b0, b1) <= bnd * bnd) done = true;
    }

    g_best[t] = fmaxf(fminf(b0, b1), 0.0f);
    if (!done) {
        int pos = atomicAdd(&g_ovfcnt, 1);   // ~2-4% of queries
        g_ovf[pos] = t;
    }
}

// Phase 2: WARP-per-query, ring-by-ring r=2..R2_CAP with per-ring exit.
// Lanes split the shell's (z,y) rows -> all lookups/scans parallel across
// lanes; warp shfl-min + warp-uniform bound check after each ring.
__global__ void __launch_bounds__(256) query2_kernel() {
    const int cnt = g_ovfcnt;
    const int lane = threadIdx.x & 31;
    const int gw = (blockIdx.x * 256 + threadIdx.x) >> 5;
    const int nw = gridDim.x * 8;
    for (int j = gw; j < cnt; j += nw) {
        const int t = g_ovf[j];
        const QInfo s = decode_query(t);
        float best = g_best[t];               // phase-1 partial
        bool done = false;

        for (int r = 2; r <= R2_CAP && !done; r++) {
            const int z0 = max(s.cz - r, 0), z1 = min(s.cz + r, G - 1);
            const int y0 = max(s.cy - r, 0), y1 = min(s.cy + r, G - 1);
            const int x0 = max(s.cx - r, 0), x1 = min(s.cx + r, G - 1);
            const int ny = y1 - y0 + 1;
            const int nzy = (z1 - z0 + 1) * ny;
            float b0 = best, b1 = CUDART_INF_F;
            for (int u = lane; u < nzy; u += 32) {
                const int z = z0 + u / ny;
                const int y = y0 + u % ny;
                const bool zf = (z == s.cz - r) || (z == s.cz + r);
                const bool yf = (y == s.cy - r) || (y == s.cy + r);
                const int rowb = s.tbase | (z << 10) | (y << 5);
                if (zf || yf) {
                    scan_range(g_start[rowb + x0], g_start[rowb + x1 + 1],
                               s.nx, s.ny, s.nz, s.qw, b0, b1);
                } else {
                    // interior row: only the two x-endpoints are on the shell
                    const int xm = s.cx - r, xp = s.cx + r;
                    if (xm >= 0)
                        scan_range(g_start[rowb + xm], g_start[rowb + xm + 1],
                                   s.nx, s.ny, s.nz, s.qw, b0, b1);
                    if (xp < G)
                        scan_range(g_start[rowb + xp], g_start[rowb + xp + 1],
                                   s.nx, s.ny, s.nz, s.qw, b0, b1);
                }
            }
            best = fminf(b0, b1);
#pragma unroll
            for (int o = 16; o >= 1; o >>= 1)
                best = fminf(best, __shfl_xor_sync(0xFFFFFFFFu, best, o));
            const float bnd = r * H + s.fmin;
            if (2.0f * fmaxf(best, 0.0f) <= bnd * bnd) done = true;  // warp-uniform
        }

        if (lane == 0) {
            g_best[t] = fmaxf(best, 0.0f);
            if (!done) {
                int pos = atomicAdd(&g_ovfcnt2, 1);   // extreme tail (~tens)
                g_ovf2[pos] = t;
            }
        }
    }
}

// Phase 3: warp-per-query brute force over the full opposing segment.
__global__ void __launch_bounds__(256) brute_kernel() {
    const int cnt = g_ovfcnt2;
    const int lane = threadIdx.x & 31;
    const int warp = (blockIdx.x * 256 + threadIdx.x) >> 5;
    for (int j = warp; j < cnt; j += 512) {
        const int t = g_ovf2[j];
        const int dir = t >> 16;
        const int qi = t & 65535;
        const int b = qi >> 13, i = qi & 8191;
        const int qseg = b * 2 + dir;
        const int tseg = b * 2 + (1 - dir);

        float4 q = g_pts[qseg * PPS + i];
        const float nx = -q.x, ny = -q.y, nz = -q.z, qw = q.w;
        const float4* tp = g_pts + tseg * PPS;

        float best = CUDART_INF_F;
        for (int k = lane; k < PPS; k += 32) {
            float4 p = tp[k];
            float d = qw + p.w;
            d = fmaf(nx, p.x, d);
            d = fmaf(ny, p.y, d);
            d = fmaf(nz, p.z, d);
            best = fminf(best, d);
        }
#pragma unroll
        for (int o = 16; o >= 1; o >>= 1)
            best = fminf(best, __shfl_xor_sync(0xFFFFFFFFu, best, o));
        if (lane == 0) g_best[t] = fmaxf(best, 0.0f);
    }
}

// Single-block deterministic sum; resets overflow counters for next call.
__global__ void final_kernel(float* __restrict__ out) {
    __shared__ float sred[1024];
    const int tid = threadIdx.x;
    float acc = 0.0f;
    const float4* p = reinterpret_cast<const float4*>(g_best);
#pragma unroll 8
    for (int i = tid; i < NQ / 4; i += 1024) {
        float4 v = p[i];
        acc += (v.x + v.y) + (v.z + v.w);
    }
    sred[tid] = acc;
    __syncthreads();
    for (int o = 512; o >= 1; o >>= 1) {
        if (tid < o) sred[tid] += sred[tid + o];
        __syncthreads();
    }
    if (tid == 0) {
        // d^2 = 2*d'; each direction is a mean over 65536 points.
        out[0] = sred[0] * (2.0f / 65536.0f);
        g_ovfcnt = 0;
        g_ovfcnt2 = 0;
    }
}

extern "C" void kernel_launch(void* const* d_in, const int* in_sizes, int n_in,
                              void* d_out, int out_size) {
    const float* gts   = (const float*)d_in[0];
    const float* preds = (const float*)d_in[1];
    float* out = (float*)d_out;

    count_kernel<<<512, 256>>>(gts, preds);
    scan1_kernel<<<SCAN_BLOCKS, 256>>>();
    scan3_kernel<<<SCAN_BLOCKS, 256>>>();
    scatter_kernel<<<512, 256>>>(gts, preds);
    query_kernel<<<512, 256>>>();
    query2_kernel<<<128, 256>>>();
    brute_kernel<<<64, 256>>>();
    final_kernel<<<1, 1024>>>(out);
}